// round 13
// baseline (speedup 1.0000x reference)
#include <cuda_runtime.h>
#include <math.h>
#include <stdint.h>

#define D_    128
#define K_    32
#define HW_   4096
#define B_    16
#define TILE_ 128
#define NT_   512

// Pad selection (pad mod 32 decides frag-load banks):
//  Xs  136 (mod32=8): phase-1 a-frag rows=tg, cols=g -> bank 8tg+g, conflict-free
//  Cs  132 (mod32=4): phase-1 b-frag rows=g, cols=tg -> bank 4g+tg, conflict-free
//  As   40 (mod32=8): phase-2 b-frag rows=tg, cols=g -> bank 8tg+g, conflict-free
//  (phase-2 a-frag on Xs is 2-way conflicted; inherent with a single pad)
#define XPAD_ 136
#define CPAD_ 132
#define APAD_ 40

#define SMEM_WORDS (D_*XPAD_ + K_*CPAD_ + TILE_*APAD_ + K_ + K_ + 4*TILE_ + 8*K_ + 4*TILE_)
#define SMEM_BYTES (SMEM_WORDS * 4)

__global__ void zero_kernel(float* out, int nelem) {
    int i = blockIdx.x * blockDim.x + threadIdx.x;
    if (i < nelem) out[i] = 0.0f;
}

__device__ __forceinline__ uint32_t f2tf(float f) {
    uint32_t u;
    asm("cvt.rna.tf32.f32 %0, %1;" : "=r"(u) : "f"(f));
    return u;
}

__device__ __forceinline__ void mma_tf32(float c[4],
                                         uint32_t a0, uint32_t a1, uint32_t a2, uint32_t a3,
                                         uint32_t b0, uint32_t b1) {
    asm volatile(
        "mma.sync.aligned.m16n8k8.row.col.f32.tf32.tf32.f32 "
        "{%0,%1,%2,%3}, {%4,%5,%6,%7}, {%8,%9}, {%0,%1,%2,%3};\n"
        : "+f"(c[0]), "+f"(c[1]), "+f"(c[2]), "+f"(c[3])
        : "r"(a0), "r"(a1), "r"(a2), "r"(a3), "r"(b0), "r"(b1));
}

__global__ __launch_bounds__(NT_, 2)
void enc_kernel(const float* __restrict__ x,
                const float* __restrict__ cw,
                const float* __restrict__ scale,
                float* __restrict__ out) {
    extern __shared__ float smem[];
    float*    Xs   = smem;                    // [D_][XPAD_]   X (fp32, later tf32 bits in place)
    float*    Cs   = Xs + D_ * XPAD_;         // [K_][CPAD_]   codewords as tf32 bits
    float*    As   = Cs + K_ * CPAD_;         // [TILE_][APAD_] softmax A as tf32 bits
    float*    c2s  = As + TILE_ * APAD_;      // [K_]
    float*    ss   = c2s + K_;                // [K_]
    float*    x2q  = ss + K_;                 // [4][TILE_]   quarter x2 sums (exact fp32)
    float*    sa8  = x2q + 4 * TILE_;         // [8][K_]
    float2*   exch = (float2*)(sa8 + 8 * K_); // [2][TILE_]   (rowmax, rowsum) per warp-half
    uint32_t* Xsb  = (uint32_t*)Xs;
    uint32_t* Csb  = (uint32_t*)Cs;
    uint32_t* Asb  = (uint32_t*)As;

    const int t    = threadIdx.x;
    const int b    = blockIdx.x >> 5;
    const int tile = blockIdx.x & 31;
    const int n0   = tile * TILE_;
    const int warp = t >> 5;
    const int lane = t & 31;
    const int g    = lane >> 2;
    const int tg   = lane & 3;
    const int half = warp >> 3;       // which 16-k half this warp covers
    const int wn   = warp & 7;        // tile-row selector
    const int k0base = half * 16;     // warp covers k in [k0base, k0base+16)

    // ---- stage C directly as tf32 bits ----
    for (int idx = t * 4; idx < K_ * D_; idx += NT_ * 4) {
        int k = idx >> 7, d = idx & 127;
        float4 v = *(const float4*)&cw[idx];
        uint4 u = make_uint4(f2tf(v.x), f2tf(v.y), f2tf(v.z), f2tf(v.w));
        *(uint4*)&Csb[k * CPAD_ + d] = u;
    }
    if (t < K_) ss[t] = scale[t];
    if (t < K_) {           // exact fp32 c2 from gmem (L2-hot)
        float s = 0.f;
        const float* c = cw + t * D_;
        #pragma unroll 8
        for (int d = 0; d < D_; d++) s += c[d] * c[d];
        c2s[t] = s;
    }

    // ---- stage X tile fp32, [d][n] ----
    const float* xb = x + (size_t)b * D_ * HW_ + n0;
    for (int idx = t * 4; idx < D_ * TILE_; idx += NT_ * 4) {
        int d = idx >> 7, c = idx & 127;
        *(float4*)&Xs[d * XPAD_ + c] = *(const float4*)&xb[(size_t)d * HW_ + c];
    }
    __syncthreads();

    // ---- x2 quarter sums, exact fp32 ----
    {
        int n = t & 127, q = t >> 7;    // q in 0..3
        float s = 0.f;
        #pragma unroll 8
        for (int d = q * 32; d < q * 32 + 32; d++) {
            float v = Xs[d * XPAD_ + n];
            s += v * v;
        }
        x2q[q * TILE_ + n] = s;
    }
    __syncthreads();

    // ---- convert X in place to tf32 bits ----
    for (int idx = t * 4; idx < D_ * TILE_; idx += NT_ * 4) {
        int d = idx >> 7, c = idx & 127;
        float4 v = *(const float4*)&Xs[d * XPAD_ + c];
        uint4 u = make_uint4(f2tf(v.x), f2tf(v.y), f2tf(v.z), f2tf(v.w));
        *(uint4*)&Xsb[d * XPAD_ + c] = u;
    }
    __syncthreads();

    // ---- Phase 1: D1[n,k] = sum_d X*C.  warp: rows [16*wn,+16), 2 k-tiles ----
    const int n0w = wn * 16;
    float c1[2][4];
    #pragma unroll
    for (int j = 0; j < 2; j++)
        #pragma unroll
        for (int i = 0; i < 4; i++) c1[j][i] = 0.f;

    #pragma unroll 4
    for (int dstep = 0; dstep < 16; dstep++) {
        int d0 = dstep * 8;
        uint32_t a0 = Xsb[(d0 + tg) * XPAD_ + n0w + g];
        uint32_t a1 = Xsb[(d0 + tg) * XPAD_ + n0w + g + 8];
        uint32_t a2 = Xsb[(d0 + tg + 4) * XPAD_ + n0w + g];
        uint32_t a3 = Xsb[(d0 + tg + 4) * XPAD_ + n0w + g + 8];
        #pragma unroll
        for (int j = 0; j < 2; j++) {
            int k0 = k0base + 8 * j;
            uint32_t b0 = Csb[(k0 + g) * CPAD_ + d0 + tg];
            uint32_t b1 = Csb[(k0 + g) * CPAD_ + d0 + tg + 4];
            mma_tf32(c1[j], a0, a1, a2, a3, b0, b1);
        }
    }

    // ---- softmax: warp-half has 16 of 32 logits per row; exchange (m,s) with partner ----
    const int r0 = n0w + g, r1 = r0 + 8;
    float l0[4], l1[4];
    {
        float x2r0 = x2q[r0] + x2q[TILE_ + r0] + x2q[2*TILE_ + r0] + x2q[3*TILE_ + r0];
        float x2r1 = x2q[r1] + x2q[TILE_ + r1] + x2q[2*TILE_ + r1] + x2q[3*TILE_ + r1];
        #pragma unroll
        for (int j = 0; j < 2; j++) {
            int k = k0base + 8 * j + 2 * tg;
            float s0 = ss[k], s1 = ss[k + 1];
            float q0 = c2s[k], q1 = c2s[k + 1];
            l0[2*j]   = s0 * (x2r0 - 2.f * c1[j][0] + q0);
            l0[2*j+1] = s1 * (x2r0 - 2.f * c1[j][1] + q1);
            l1[2*j]   = s0 * (x2r1 - 2.f * c1[j][2] + q0);
            l1[2*j+1] = s1 * (x2r1 - 2.f * c1[j][3] + q1);
        }
    }
    float m0 = fmaxf(fmaxf(l0[0], l0[1]), fmaxf(l0[2], l0[3]));
    float m1 = fmaxf(fmaxf(l1[0], l1[1]), fmaxf(l1[2], l1[3]));
    m0 = fmaxf(m0, __shfl_xor_sync(0xffffffffu, m0, 1));
    m0 = fmaxf(m0, __shfl_xor_sync(0xffffffffu, m0, 2));
    m1 = fmaxf(m1, __shfl_xor_sync(0xffffffffu, m1, 1));
    m1 = fmaxf(m1, __shfl_xor_sync(0xffffffffu, m1, 2));
    float s0 = 0.f, s1 = 0.f;
    #pragma unroll
    for (int i = 0; i < 4; i++) {
        l0[i] = __expf(l0[i] - m0); s0 += l0[i];
        l1[i] = __expf(l1[i] - m1); s1 += l1[i];
    }
    s0 += __shfl_xor_sync(0xffffffffu, s0, 1);
    s0 += __shfl_xor_sync(0xffffffffu, s0, 2);
    s1 += __shfl_xor_sync(0xffffffffu, s1, 1);
    s1 += __shfl_xor_sync(0xffffffffu, s1, 2);
    if (tg == 0) {
        exch[half * TILE_ + r0] = make_float2(m0, s0);
        exch[half * TILE_ + r1] = make_float2(m1, s1);
    }
    __syncthreads();
    {
        float2 p0 = exch[(1 - half) * TILE_ + r0];
        float2 p1 = exch[(1 - half) * TILE_ + r1];
        float M0 = fmaxf(m0, p0.x), M1 = fmaxf(m1, p1.x);
        float S0 = s0 * __expf(m0 - M0) + p0.y * __expf(p0.x - M0);
        float S1 = s1 * __expf(m1 - M1) + p1.y * __expf(p1.x - M1);
        float f0 = __expf(m0 - M0) / S0;
        float f1 = __expf(m1 - M1) / S1;
        #pragma unroll
        for (int j = 0; j < 2; j++) {
            int k = k0base + 8 * j + 2 * tg;
            *(uint2*)&Asb[r0 * APAD_ + k] = make_uint2(f2tf(l0[2*j] * f0), f2tf(l0[2*j+1] * f0));
            *(uint2*)&Asb[r1 * APAD_ + k] = make_uint2(f2tf(l1[2*j] * f1), f2tf(l1[2*j+1] * f1));
        }
    }
    __syncthreads();

    // ---- sa partials (reading tf32-bit A as float gives the rounded value) ----
    if (warp < 8) {
        float s = 0.f;
        #pragma unroll
        for (int n = warp * 16; n < warp * 16 + 16; n++) s += As[n * APAD_ + lane];
        sa8[warp * K_ + lane] = s;
    }

    // ---- Phase 2: E^T[d,k] = sum_n X[n,d]*A[n,k].  warp: d rows [16*wn,+16), 2 k-tiles ----
    const int d0w = wn * 16;
    float c2f[2][4];
    #pragma unroll
    for (int j = 0; j < 2; j++)
        #pragma unroll
        for (int i = 0; i < 4; i++) c2f[j][i] = 0.f;

    #pragma unroll 4
    for (int nstep = 0; nstep < 16; nstep++) {
        int nk0 = nstep * 8;
        uint32_t a0 = Xsb[(d0w + g) * XPAD_ + nk0 + tg];
        uint32_t a1 = Xsb[(d0w + g + 8) * XPAD_ + nk0 + tg];
        uint32_t a2 = Xsb[(d0w + g) * XPAD_ + nk0 + tg + 4];
        uint32_t a3 = Xsb[(d0w + g + 8) * XPAD_ + nk0 + tg + 4];
        #pragma unroll
        for (int j = 0; j < 2; j++) {
            int k0 = k0base + 8 * j;
            uint32_t b0 = Asb[(nk0 + tg) * APAD_ + k0 + g];
            uint32_t b1 = Asb[(nk0 + tg + 4) * APAD_ + k0 + g];
            mma_tf32(c2f[j], a0, a1, a2, a3, b0, b1);
        }
    }
    __syncthreads();   // sa8 complete before epilogue reads it

    // ---- epilogue: out[b][k][d] += E^T[d][k] - sa[k]*C[k][d]  (fp32 C from gmem, L2-hot) ----
    float* ob = out + b * K_ * D_;
    #pragma unroll
    for (int j = 0; j < 2; j++) {
        int k = k0base + 8 * j + 2 * tg;
        float saA = 0.f, saB = 0.f;
        #pragma unroll
        for (int w = 0; w < 8; w++) {
            saA += sa8[w * K_ + k];
            saB += sa8[w * K_ + k + 1];
        }
        int dA = d0w + g, dB = dA + 8;
        atomicAdd(&ob[k       * D_ + dA], c2f[j][0] - saA * cw[k       * D_ + dA]);
        atomicAdd(&ob[(k + 1) * D_ + dA], c2f[j][1] - saB * cw[(k + 1) * D_ + dA]);
        atomicAdd(&ob[k       * D_ + dB], c2f[j][2] - saA * cw[k       * D_ + dB]);
        atomicAdd(&ob[(k + 1) * D_ + dB], c2f[j][3] - saB * cw[(k + 1) * D_ + dB]);
    }
}

extern "C" void kernel_launch(void* const* d_in, const int* in_sizes, int n_in,
                              void* d_out, int out_size) {
    const float* x  = (const float*)d_in[0];   // (B, D, H, W) fp32
    const float* cw = (const float*)d_in[1];   // (K, D) fp32
    const float* sc = (const float*)d_in[2];   // (K,) fp32
    float* out = (float*)d_out;                // (B, K, D) fp32

    cudaFuncSetAttribute(enc_kernel, cudaFuncAttributeMaxDynamicSharedMemorySize, SMEM_BYTES);

    const int nelem = B_ * K_ * D_;
    zero_kernel<<<(nelem + 255) / 256, 256>>>(out, nelem);
    enc_kernel<<<B_ * (HW_ / TILE_), NT_, SMEM_BYTES>>>(x, cw, sc, out);
}

// round 14
// speedup vs baseline: 1.0625x; 1.0625x over previous
#include <cuda_runtime.h>
#include <math.h>
#include <stdint.h>

#define D_    128
#define K_    32
#define HW_   4096
#define B_    16
#define TILE_ 128
#define NT_   512

// Pad selection (pad mod 32 decides frag-load banks):
//  Xs  136 (mod32=8): phase-1 a-frag rows=tg, cols=g -> bank 8tg+g, conflict-free
//  Cs  132 (mod32=4): phase-1 b-frag rows=g, cols=tg -> bank 4g+tg, conflict-free
//  As   40 (mod32=8): phase-2 b-frag rows=tg, cols=g -> bank 8tg+g, conflict-free
#define XPAD_ 136
#define CPAD_ 132
#define APAD_ 40

#define SMEM_WORDS (D_*XPAD_ + K_*CPAD_ + TILE_*APAD_ + K_ + K_ + 4*TILE_ + 8*K_ + 4*TILE_)
#define SMEM_BYTES (SMEM_WORDS * 4)

__global__ void zero_kernel(float* out, int nelem) {
    int i = blockIdx.x * blockDim.x + threadIdx.x;
    if (i < nelem) out[i] = 0.0f;
}

__device__ __forceinline__ uint32_t f2tf(float f) {
    uint32_t u;
    asm("cvt.rna.tf32.f32 %0, %1;" : "=r"(u) : "f"(f));
    return u;
}

__device__ __forceinline__ void mma_tf32(float c[4],
                                         uint32_t a0, uint32_t a1, uint32_t a2, uint32_t a3,
                                         uint32_t b0, uint32_t b1) {
    asm volatile(
        "mma.sync.aligned.m16n8k8.row.col.f32.tf32.tf32.f32 "
        "{%0,%1,%2,%3}, {%4,%5,%6,%7}, {%8,%9}, {%0,%1,%2,%3};\n"
        : "+f"(c[0]), "+f"(c[1]), "+f"(c[2]), "+f"(c[3])
        : "r"(a0), "r"(a1), "r"(a2), "r"(a3), "r"(b0), "r"(b1));
}

__global__ __launch_bounds__(NT_, 2)
void enc_kernel(const float* __restrict__ x,
                const float* __restrict__ cw,
                const float* __restrict__ scale,
                float* __restrict__ out) {
    extern __shared__ float smem[];
    float*    Xs   = smem;                    // [D_][XPAD_]   X as tf32 bits
    float*    Cs   = Xs + D_ * XPAD_;         // [K_][CPAD_]   codewords as tf32 bits
    float*    As   = Cs + K_ * CPAD_;         // [TILE_][APAD_] scratch x2 partials -> softmax A
    float*    c2s  = As + TILE_ * APAD_;      // [K_]
    float*    ss   = c2s + K_;                // [K_]
    float*    x2a  = ss + K_;                 // [TILE_] final x2 (+ spare)
    float*    sa8  = x2a + 4 * TILE_;         // [8][K_]
    float2*   exch = (float2*)(sa8 + 8 * K_); // [2][TILE_]
    uint32_t* Xsb  = (uint32_t*)Xs;
    uint32_t* Csb  = (uint32_t*)Cs;
    uint32_t* Asb  = (uint32_t*)As;

    const int t    = threadIdx.x;
    const int b    = blockIdx.x >> 5;
    const int tile = blockIdx.x & 31;
    const int n0   = tile * TILE_;
    const int warp = t >> 5;
    const int lane = t & 31;
    const int g    = lane >> 2;
    const int tg   = lane & 3;
    const int half = warp >> 3;       // 16-k half
    const int wn   = warp & 7;        // row-strip
    const int k0base = half * 16;

    // ---- stage C as tf32 bits ----
    for (int idx = t * 4; idx < K_ * D_; idx += NT_ * 4) {
        int k = idx >> 7, d = idx & 127;
        float4 v = *(const float4*)&cw[idx];
        uint4 u = make_uint4(f2tf(v.x), f2tf(v.y), f2tf(v.z), f2tf(v.w));
        *(uint4*)&Csb[k * CPAD_ + d] = u;
    }
    if (t < K_) ss[t] = scale[t];
    if (t < K_) {           // exact fp32 c2 from gmem (L2-hot)
        float s = 0.f;
        const float* c = cw + t * D_;
        #pragma unroll 8
        for (int d = 0; d < D_; d++) s += c[d] * c[d];
        c2s[t] = s;
    }

    // ---- FUSED: stage X -> tf32 bits + x2 partial accumulation ----
    // thread t covers columns c..c+3 for d = warp + 16*i  (i = 0..7)
    const float* xb = x + (size_t)b * D_ * HW_ + n0;
    {
        const int c = lane * 4;
        float4 acc = make_float4(0.f, 0.f, 0.f, 0.f);
        #pragma unroll
        for (int i = 0; i < 8; i++) {
            int d = warp + 16 * i;
            float4 v = *(const float4*)&xb[(size_t)d * HW_ + c];
            acc.x += v.x * v.x; acc.y += v.y * v.y;
            acc.z += v.z * v.z; acc.w += v.w * v.w;
            uint4 u = make_uint4(f2tf(v.x), f2tf(v.y), f2tf(v.z), f2tf(v.w));
            *(uint4*)&Xsb[d * XPAD_ + c] = u;
        }
        *(float4*)&As[warp * TILE_ + c] = acc;   // [16][128] scratch in As region
    }
    __syncthreads();

    // ---- x2 finalize (threads 0..127); other warps fall through to phase 1 ----
    if (t < TILE_) {
        float s = 0.f;
        #pragma unroll
        for (int p = 0; p < 16; p++) s += As[p * TILE_ + t];
        x2a[t] = s;
    }

    // ---- Phase 1: D1[n,k] = sum_d X*C.  warp: rows [16*wn,+16), 2 k-tiles ----
    const int n0w = wn * 16;
    float c1[2][4];
    #pragma unroll
    for (int j = 0; j < 2; j++)
        #pragma unroll
        for (int i = 0; i < 4; i++) c1[j][i] = 0.f;

    #pragma unroll 4
    for (int dstep = 0; dstep < 16; dstep++) {
        int d0 = dstep * 8;
        uint32_t a0 = Xsb[(d0 + tg) * XPAD_ + n0w + g];
        uint32_t a1 = Xsb[(d0 + tg) * XPAD_ + n0w + g + 8];
        uint32_t a2 = Xsb[(d0 + tg + 4) * XPAD_ + n0w + g];
        uint32_t a3 = Xsb[(d0 + tg + 4) * XPAD_ + n0w + g + 8];
        #pragma unroll
        for (int j = 0; j < 2; j++) {
            int k0 = k0base + 8 * j;
            uint32_t b0 = Csb[(k0 + g) * CPAD_ + d0 + tg];
            uint32_t b1 = Csb[(k0 + g) * CPAD_ + d0 + tg + 4];
            mma_tf32(c1[j], a0, a1, a2, a3, b0, b1);
        }
    }
    __syncthreads();   // x2a ready; As scratch reads complete (As now reusable for A)

    // ---- softmax: warp-half has 16 of 32 logits per row; (m,s) exchange with partner ----
    const int r0 = n0w + g, r1 = r0 + 8;
    float l0[4], l1[4];
    {
        float x2r0 = x2a[r0];
        float x2r1 = x2a[r1];
        #pragma unroll
        for (int j = 0; j < 2; j++) {
            int k = k0base + 8 * j + 2 * tg;
            float s0 = ss[k], s1 = ss[k + 1];
            float q0 = c2s[k], q1 = c2s[k + 1];
            l0[2*j]   = s0 * (x2r0 - 2.f * c1[j][0] + q0);
            l0[2*j+1] = s1 * (x2r0 - 2.f * c1[j][1] + q1);
            l1[2*j]   = s0 * (x2r1 - 2.f * c1[j][2] + q0);
            l1[2*j+1] = s1 * (x2r1 - 2.f * c1[j][3] + q1);
        }
    }
    float m0 = fmaxf(fmaxf(l0[0], l0[1]), fmaxf(l0[2], l0[3]));
    float m1 = fmaxf(fmaxf(l1[0], l1[1]), fmaxf(l1[2], l1[3]));
    m0 = fmaxf(m0, __shfl_xor_sync(0xffffffffu, m0, 1));
    m0 = fmaxf(m0, __shfl_xor_sync(0xffffffffu, m0, 2));
    m1 = fmaxf(m1, __shfl_xor_sync(0xffffffffu, m1, 1));
    m1 = fmaxf(m1, __shfl_xor_sync(0xffffffffu, m1, 2));
    float s0 = 0.f, s1 = 0.f;
    #pragma unroll
    for (int i = 0; i < 4; i++) {
        l0[i] = __expf(l0[i] - m0); s0 += l0[i];
        l1[i] = __expf(l1[i] - m1); s1 += l1[i];
    }
    s0 += __shfl_xor_sync(0xffffffffu, s0, 1);
    s0 += __shfl_xor_sync(0xffffffffu, s0, 2);
    s1 += __shfl_xor_sync(0xffffffffu, s1, 1);
    s1 += __shfl_xor_sync(0xffffffffu, s1, 2);
    if (tg == 0) {
        exch[half * TILE_ + r0] = make_float2(m0, s0);
        exch[half * TILE_ + r1] = make_float2(m1, s1);
    }
    __syncthreads();
    {
        float2 p0 = exch[(1 - half) * TILE_ + r0];
        float2 p1 = exch[(1 - half) * TILE_ + r1];
        float M0 = fmaxf(m0, p0.x), M1 = fmaxf(m1, p1.x);
        float S0 = s0 * __expf(m0 - M0) + p0.y * __expf(p0.x - M0);
        float S1 = s1 * __expf(m1 - M1) + p1.y * __expf(p1.x - M1);
        float f0 = __expf(m0 - M0) / S0;
        float f1 = __expf(m1 - M1) / S1;
        #pragma unroll
        for (int j = 0; j < 2; j++) {
            int k = k0base + 8 * j + 2 * tg;
            *(uint2*)&Asb[r0 * APAD_ + k] = make_uint2(f2tf(l0[2*j] * f0), f2tf(l0[2*j+1] * f0));
            *(uint2*)&Asb[r1 * APAD_ + k] = make_uint2(f2tf(l1[2*j] * f1), f2tf(l1[2*j+1] * f1));
        }
    }
    __syncthreads();

    // ---- sa partials ----
    if (warp < 8) {
        float s = 0.f;
        #pragma unroll
        for (int n = warp * 16; n < warp * 16 + 16; n++) s += As[n * APAD_ + lane];
        sa8[warp * K_ + lane] = s;
    }

    // ---- Phase 2: E^T[d,k] = sum_n X[n,d]*A[n,k] ----
    const int d0w = wn * 16;
    float c2f[2][4];
    #pragma unroll
    for (int j = 0; j < 2; j++)
        #pragma unroll
        for (int i = 0; i < 4; i++) c2f[j][i] = 0.f;

    #pragma unroll 4
    for (int nstep = 0; nstep < 16; nstep++) {
        int nk0 = nstep * 8;
        uint32_t a0 = Xsb[(d0w + g) * XPAD_ + nk0 + tg];
        uint32_t a1 = Xsb[(d0w + g + 8) * XPAD_ + nk0 + tg];
        uint32_t a2 = Xsb[(d0w + g) * XPAD_ + nk0 + tg + 4];
        uint32_t a3 = Xsb[(d0w + g + 8) * XPAD_ + nk0 + tg + 4];
        #pragma unroll
        for (int j = 0; j < 2; j++) {
            int k0 = k0base + 8 * j;
            uint32_t b0 = Asb[(nk0 + tg) * APAD_ + k0 + g];
            uint32_t b1 = Asb[(nk0 + tg + 4) * APAD_ + k0 + g];
            mma_tf32(c2f[j], a0, a1, a2, a3, b0, b1);
        }
    }
    __syncthreads();   // sa8 complete before epilogue reads it

    // ---- epilogue ----
    float* ob = out + b * K_ * D_;
    #pragma unroll
    for (int j = 0; j < 2; j++) {
        int k = k0base + 8 * j + 2 * tg;
        float saA = 0.f, saB = 0.f;
        #pragma unroll
        for (int w = 0; w < 8; w++) {
            saA += sa8[w * K_ + k];
            saB += sa8[w * K_ + k + 1];
        }
        int dA = d0w + g, dB = dA + 8;
        atomicAdd(&ob[k       * D_ + dA], c2f[j][0] - saA * cw[k       * D_ + dA]);
        atomicAdd(&ob[(k + 1) * D_ + dA], c2f[j][1] - saB * cw[(k + 1) * D_ + dA]);
        atomicAdd(&ob[k       * D_ + dB], c2f[j][2] - saA * cw[k       * D_ + dB]);
        atomicAdd(&ob[(k + 1) * D_ + dB], c2f[j][3] - saB * cw[(k + 1) * D_ + dB]);
    }
}

extern "C" void kernel_launch(void* const* d_in, const int* in_sizes, int n_in,
                              void* d_out, int out_size) {
    const float* x  = (const float*)d_in[0];   // (B, D, H, W) fp32
    const float* cw = (const float*)d_in[1];   // (K, D) fp32
    const float* sc = (const float*)d_in[2];   // (K,) fp32
    float* out = (float*)d_out;                // (B, K, D) fp32

    cudaFuncSetAttribute(enc_kernel, cudaFuncAttributeMaxDynamicSharedMemorySize, SMEM_BYTES);

    const int nelem = B_ * K_ * D_;
    zero_kernel<<<(nelem + 255) / 256, 256>>>(out, nelem);
    enc_kernel<<<B_ * (HW_ / TILE_), NT_, SMEM_BYTES>>>(x, cw, sc, out);
}

// round 16
// speedup vs baseline: 1.5888x; 1.4953x over previous
#include <cuda_runtime.h>
#include <cuda_fp16.h>
#include <math.h>
#include <stdint.h>

#define D_    128
#define K_    32
#define HW_   4096
#define B_    16
#define TILE_ 128
#define NT_   256

#define XH_ 136   // halves per row; word-stride 68 (mod32=4): half2 frag banks 4g+tg, conflict-free
#define CH_ 136
#define AH_ 136

// bytes: Xdn 34816 + C 8704 + AT 8704 + c2s 128 + ss 128 + x2a 512 + sa8 1024 + saf 128
#define SMEM_BYTES (34816 + 8704 + 8704 + 128 + 128 + 512 + 1024 + 128)

__global__ void zero_kernel(float* out, int nelem) {
    int i = blockIdx.x * blockDim.x + threadIdx.x;
    if (i < nelem) out[i] = 0.0f;
}

__device__ __forceinline__ void mma_f16(float c[4],
                                        uint32_t a0, uint32_t a1, uint32_t a2, uint32_t a3,
                                        uint32_t b0, uint32_t b1) {
    asm volatile(
        "mma.sync.aligned.m16n8k16.row.col.f32.f16.f16.f32 "
        "{%0,%1,%2,%3}, {%4,%5,%6,%7}, {%8,%9}, {%0,%1,%2,%3};\n"
        : "+f"(c[0]), "+f"(c[1]), "+f"(c[2]), "+f"(c[3])
        : "r"(a0), "r"(a1), "r"(a2), "r"(a3), "r"(b0), "r"(b1));
}

__global__ __launch_bounds__(NT_, 4)
void enc_kernel(const float* __restrict__ x,
                const float* __restrict__ cw,
                const float* __restrict__ scale,
                float* __restrict__ out) {
    extern __shared__ char smem[];
    __half*   Xh  = (__half*)smem;                    // [128 d][136 n]  X fp16
    __half*   Ch  = Xh + 128 * XH_;                   // [32 k][136 d]   C fp16
    __half*   ATh = Ch + 32 * CH_;                    // [32 k][136 n]   A^T fp16 (softmax out)
    float*    scr = (float*)ATh;                      // [8][128] x2 scratch (aliased, pre-softmax)
    float*    c2s = (float*)(ATh + 32 * AH_);         // [32]
    float*    ss  = c2s + K_;                         // [32]
    float*    x2a = ss + K_;                          // [128]
    float*    sa8 = x2a + TILE_;                      // [8][32]
    float*    saf = sa8 + 8 * K_;                     // [32]
    const uint16_t* Xu = (const uint16_t*)Xh;

    const int t    = threadIdx.x;
    const int b    = blockIdx.x >> 5;
    const int tile = blockIdx.x & 31;
    const int n0   = tile * TILE_;
    const int warp = t >> 5;
    const int lane = t & 31;
    const int g    = lane >> 2;
    const int tg   = lane & 3;

    // ---- stage C as fp16 (4096 floats; 4 float4 per thread) ----
    for (int idx = t * 4; idx < K_ * D_; idx += NT_ * 4) {
        int k = idx >> 7, d = idx & 127;
        float4 v = *(const float4*)&cw[idx];
        __half2 h0 = __floats2half2_rn(v.x, v.y);
        __half2 h1 = __floats2half2_rn(v.z, v.w);
        uint2 u;
        u.x = *(uint32_t*)&h0; u.y = *(uint32_t*)&h1;
        *(uint2*)&Ch[k * CH_ + d] = u;
    }
    if (t < K_) ss[t] = scale[t];
    if (t < K_) {           // exact fp32 c2 from gmem (L2-hot)
        float s = 0.f;
        const float* c = cw + t * D_;
        #pragma unroll 8
        for (int d = 0; d < D_; d++) s += c[d] * c[d];
        c2s[t] = s;
    }

    // ---- FUSED: stage X -> fp16 [d][n] + exact-fp32 x2 partials ----
    // lane covers n-cols 4l..4l+3 for d = warp + 8*i
    const float* xb = x + (size_t)b * D_ * HW_ + n0;
    {
        const int c = lane * 4;
        float4 acc = make_float4(0.f, 0.f, 0.f, 0.f);
        #pragma unroll
        for (int i = 0; i < 16; i++) {
            int d = warp + 8 * i;
            float4 v = *(const float4*)&xb[(size_t)d * HW_ + c];
            acc.x += v.x * v.x; acc.y += v.y * v.y;
            acc.z += v.z * v.z; acc.w += v.w * v.w;
            __half2 h0 = __floats2half2_rn(v.x, v.y);
            __half2 h1 = __floats2half2_rn(v.z, v.w);
            uint2 u;
            u.x = *(uint32_t*)&h0; u.y = *(uint32_t*)&h1;
            *(uint2*)&Xh[d * XH_ + c] = u;
        }
        *(float4*)&scr[warp * TILE_ + c] = acc;
    }
    __syncthreads();

    // ---- x2 finalize (t<128) ----
    if (t < TILE_) {
        float s = 0.f;
        #pragma unroll
        for (int w = 0; w < 8; w++) s += scr[w * TILE_ + t];
        x2a[t] = s;
    }

    // ---- Phase 1: D1[n,k] = sum_d X[n,d]*C[k,d].  warp: 16 n-rows, all 4 k-tiles ----
    const int n0w = warp * 16;
    float c1[4][4];
    #pragma unroll
    for (int kt = 0; kt < 4; kt++)
        #pragma unroll
        for (int i = 0; i < 4; i++) c1[kt][i] = 0.f;

    #pragma unroll
    for (int ds = 0; ds < 8; ds++) {
        int d0 = ds * 16;
        // a-frags: rows(k-dim)=d, cols(M)=n. 2x LDS.16 + pack each; broadcast pairs, conflict-free
        int r0 = d0 + 2 * tg, r1 = r0 + 1, r2 = r0 + 8, r3 = r0 + 9;
        int cA = n0w + g, cB = cA + 8;
        uint32_t a0 = (uint32_t)Xu[r0 * XH_ + cA] | ((uint32_t)Xu[r1 * XH_ + cA] << 16);
        uint32_t a1 = (uint32_t)Xu[r0 * XH_ + cB] | ((uint32_t)Xu[r1 * XH_ + cB] << 16);
        uint32_t a2 = (uint32_t)Xu[r2 * XH_ + cA] | ((uint32_t)Xu[r3 * XH_ + cA] << 16);
        uint32_t a3 = (uint32_t)Xu[r2 * XH_ + cB] | ((uint32_t)Xu[r3 * XH_ + cB] << 16);
        #pragma unroll
        for (int kt = 0; kt < 4; kt++) {
            int k0 = kt * 8;
            uint32_t b0 = *(const uint32_t*)&Ch[(k0 + g) * CH_ + d0 + 2 * tg];
            uint32_t b1 = *(const uint32_t*)&Ch[(k0 + g) * CH_ + d0 + 2 * tg + 8];
            mma_f16(c1[kt], a0, a1, a2, a3, b0, b1);
        }
    }
    __syncthreads();   // x2a ready; scr reads done (ATh region now writable)

    // ---- softmax over K=32 (in-thread 8 + shuffles over tg) ----
    const int r0 = n0w + g, r1 = r0 + 8;
    float l0[8], l1[8];
    {
        float x2r0 = x2a[r0], x2r1 = x2a[r1];
        #pragma unroll
        for (int kt = 0; kt < 4; kt++) {
            int k = kt * 8 + 2 * tg;
            float s0 = ss[k], s1 = ss[k + 1];
            float q0 = c2s[k], q1 = c2s[k + 1];
            l0[2*kt]   = s0 * (x2r0 - 2.f * c1[kt][0] + q0);
            l0[2*kt+1] = s1 * (x2r0 - 2.f * c1[kt][1] + q1);
            l1[2*kt]   = s0 * (x2r1 - 2.f * c1[kt][2] + q0);
            l1[2*kt+1] = s1 * (x2r1 - 2.f * c1[kt][3] + q1);
        }
    }
    float m0 = -1e30f, m1 = -1e30f;
    #pragma unroll
    for (int i = 0; i < 8; i++) { m0 = fmaxf(m0, l0[i]); m1 = fmaxf(m1, l1[i]); }
    m0 = fmaxf(m0, __shfl_xor_sync(0xffffffffu, m0, 1));
    m0 = fmaxf(m0, __shfl_xor_sync(0xffffffffu, m0, 2));
    m1 = fmaxf(m1, __shfl_xor_sync(0xffffffffu, m1, 1));
    m1 = fmaxf(m1, __shfl_xor_sync(0xffffffffu, m1, 2));
    float s0 = 0.f, s1 = 0.f;
    #pragma unroll
    for (int i = 0; i < 8; i++) {
        l0[i] = __expf(l0[i] - m0); s0 += l0[i];
        l1[i] = __expf(l1[i] - m1); s1 += l1[i];
    }
    s0 += __shfl_xor_sync(0xffffffffu, s0, 1);
    s0 += __shfl_xor_sync(0xffffffffu, s0, 2);
    s1 += __shfl_xor_sync(0xffffffffu, s1, 1);
    s1 += __shfl_xor_sync(0xffffffffu, s1, 2);
    float i0 = 1.f / s0, i1 = 1.f / s1;

    // write A^T[k][n] fp16 + sa via register shuffles
    float saP[8];
    #pragma unroll
    for (int kt = 0; kt < 4; kt++) {
        #pragma unroll
        for (int c = 0; c < 2; c++) {
            int k = kt * 8 + 2 * tg + c;
            float a0v = l0[2*kt+c] * i0;
            float a1v = l1[2*kt+c] * i1;
            ((uint16_t*)ATh)[k * AH_ + r0] = __half_as_ushort(__float2half_rn(a0v));
            ((uint16_t*)ATh)[k * AH_ + r1] = __half_as_ushort(__float2half_rn(a1v));
            saP[2*kt+c] = a0v + a1v;
        }
    }
    #pragma unroll
    for (int i = 0; i < 8; i++) {
        saP[i] += __shfl_xor_sync(0xffffffffu, saP[i], 4);
        saP[i] += __shfl_xor_sync(0xffffffffu, saP[i], 8);
        saP[i] += __shfl_xor_sync(0xffffffffu, saP[i], 16);
    }
    if (lane < 4) {
        #pragma unroll
        for (int kt = 0; kt < 4; kt++) {
            sa8[warp * K_ + kt * 8 + 2 * lane]     = saP[2*kt];
            sa8[warp * K_ + kt * 8 + 2 * lane + 1] = saP[2*kt+1];
        }
    }
    __syncthreads();

    // ---- sa finalize (t<32) runs alongside phase 2 ----
    if (t < K_) {
        float s = 0.f;
        #pragma unroll
        for (int w = 0; w < 8; w++) s += sa8[w * K_ + t];
        saf[t] = s;
    }

    // ---- Phase 2: E^T[d,k] = sum_n X[n,d]*A[n,k].  warp: 16 d-rows, 4 k-tiles ----
    const int d0w = warp * 16;
    float c2f[4][4];
    #pragma unroll
    for (int kt = 0; kt < 4; kt++)
        #pragma unroll
        for (int i = 0; i < 4; i++) c2f[kt][i] = 0.f;

    #pragma unroll
    for (int ns = 0; ns < 8; ns++) {
        int nk0 = ns * 16;
        uint32_t a0 = *(const uint32_t*)&Xh[(d0w + g) * XH_ + nk0 + 2 * tg];
        uint32_t a1 = *(const uint32_t*)&Xh[(d0w + g + 8) * XH_ + nk0 + 2 * tg];
        uint32_t a2 = *(const uint32_t*)&Xh[(d0w + g) * XH_ + nk0 + 2 * tg + 8];
        uint32_t a3 = *(const uint32_t*)&Xh[(d0w + g + 8) * XH_ + nk0 + 2 * tg + 8];
        #pragma unroll
        for (int kt = 0; kt < 4; kt++) {
            int k0 = kt * 8;
            uint32_t b0 = *(const uint32_t*)&ATh[(k0 + g) * AH_ + nk0 + 2 * tg];
            uint32_t b1 = *(const uint32_t*)&ATh[(k0 + g) * AH_ + nk0 + 2 * tg + 8];
            mma_f16(c2f[kt], a0, a1, a2, a3, b0, b1);
        }
    }
    __syncthreads();   // saf ready

    // ---- epilogue: out[b][k][d] += E^T[d][k] - sa[k]*C[k][d]  (exact fp32 C from gmem) ----
    float* ob = out + b * K_ * D_;
    #pragma unroll
    for (int kt = 0; kt < 4; kt++) {
        int k = kt * 8 + 2 * tg;
        float saA = saf[k], saB = saf[k + 1];
        int dA = d0w + g, dB = dA + 8;
        atomicAdd(&ob[k       * D_ + dA], c2f[kt][0] - saA * cw[k       * D_ + dA]);
        atomicAdd(&ob[(k + 1) * D_ + dA], c2f[kt][1] - saB * cw[(k + 1) * D_ + dA]);
        atomicAdd(&ob[k       * D_ + dB], c2f[kt][2] - saA * cw[k       * D_ + dB]);
        atomicAdd(&ob[(k + 1) * D_ + dB], c2f[kt][3] - saB * cw[(k + 1) * D_ + dB]);
    }
}

extern "C" void kernel_launch(void* const* d_in, const int* in_sizes, int n_in,
                              void* d_out, int out_size) {
    const float* x  = (const float*)d_in[0];   // (B, D, H, W) fp32
    const float* cw = (const float*)d_in[1];   // (K, D) fp32
    const float* sc = (const float*)d_in[2];   // (K,) fp32
    float* out = (float*)d_out;                // (B, K, D) fp32

    cudaFuncSetAttribute(enc_kernel, cudaFuncAttributeMaxDynamicSharedMemorySize, SMEM_BYTES);

    const int nelem = B_ * K_ * D_;
    zero_kernel<<<(nelem + 255) / 256, 256>>>(out, nelem);
    enc_kernel<<<B_ * (HW_ / TILE_), NT_, SMEM_BYTES>>>(x, cw, sc, out);
}